// round 1
// baseline (speedup 1.0000x reference)
#include <cuda_runtime.h>
#include <cuda_bf16.h>

// Haar 3D wavelet transform, causal time pad (replicate first frame).
// x:  [B=2, C=3, T=33, H=512, W=512] fp32
// out:[B=2, 8*C=24, Tp=17, Hp=256, Wp=256] fp32, sub-band major (s*C + c)
//
// out[b, s*C+c, tp, hp, wp] = SCALE * sum_{dt,dh,dw} (-1)^(dt*st+dh*sh+dw*sw)
//                              * xp[b,c,2tp+dt,2hp+dh,2wp+dw]
// where xp[t'] = x[max(t'-1,0)]  (causal pad: one replicated frame at front)

#define SCALE 0.3536f

static constexpr int B  = 2;
static constexpr int C  = 3;
static constexpr int T  = 33;
static constexpr int H  = 512;
static constexpr int W  = 512;
static constexpr int Tp = 17;
static constexpr int Hp = 256;
static constexpr int Wp = 256;
static constexpr int WP2 = Wp / 2;   // each thread covers 2 wp (one float4 of input W)

static constexpr long TOTAL_THREADS = (long)B * C * Tp * Hp * WP2; // 3,342,336
static constexpr long OUT_CH_STRIDE = (long)Tp * Hp * Wp;          // per-channel elems
static constexpr long IN_FRAME     = (long)H * W;                  // per-frame elems

__global__ __launch_bounds__(256)
void haar3d_kernel(const float* __restrict__ x, float* __restrict__ out) {
    long idx = (long)blockIdx.x * blockDim.x + threadIdx.x;
    if (idx >= TOTAL_THREADS) return;

    int w4 = (int)(idx % WP2);          // float4 index along W
    long r  = idx / WP2;
    int hp = (int)(r % Hp); r /= Hp;
    int tp = (int)(r % Tp); r /= Tp;
    int c  = (int)(r % C);
    int b  = (int)(r / C);

    int t1 = 2 * tp;                    // xp[2tp+1] -> x[2tp]
    int t0 = t1 - 1; if (t0 < 0) t0 = 0;// xp[2tp]   -> x[2tp-1], clamped
    int h0 = 2 * hp;

    const long inBase = ((long)(b * C + c) * T) * IN_FRAME;
    const float4* __restrict__ x4 = (const float4*)x;
    // row index in float4 units: (frame*H + h)*W/4 + w4
    long r00 = (inBase + (long)t0 * IN_FRAME + (long)(h0    ) * W) / 4 + w4;
    long r01 = (inBase + (long)t0 * IN_FRAME + (long)(h0 + 1) * W) / 4 + w4;
    long r10 = (inBase + (long)t1 * IN_FRAME + (long)(h0    ) * W) / 4 + w4;
    long r11 = (inBase + (long)t1 * IN_FRAME + (long)(h0 + 1) * W) / 4 + w4;

    float4 a00 = x4[r00];   // (dt=0, dh=0): lanes [w0 w0' | w1 w1']
    float4 a01 = x4[r01];   // (dt=0, dh=1)
    float4 a10 = x4[r10];   // (dt=1, dh=0)
    float4 a11 = x4[r11];   // (dt=1, dh=1)

    // Butterfly per output lane (2 wp lanes: .x/.y and .z/.w)
    float res[8][2];
    #pragma unroll
    for (int lane = 0; lane < 2; lane++) {
        float p000, p001, p010, p011, p100, p101, p110, p111; // [dt][dh][dw]
        if (lane == 0) {
            p000 = a00.x; p001 = a00.y;
            p010 = a01.x; p011 = a01.y;
            p100 = a10.x; p101 = a10.y;
            p110 = a11.x; p111 = a11.y;
        } else {
            p000 = a00.z; p001 = a00.w;
            p010 = a01.z; p011 = a01.w;
            p100 = a10.z; p101 = a10.w;
            p110 = a11.z; p111 = a11.w;
        }
        // W stage (dw): sum / diff
        float w00s = p000 + p001, w00d = p000 - p001;
        float w01s = p010 + p011, w01d = p010 - p011;
        float w10s = p100 + p101, w10d = p100 - p101;
        float w11s = p110 + p111, w11d = p110 - p111;
        // H stage (dh)
        float h0s_s = w00s + w01s, h0d_s = w00s - w01s;   // (dw-sum) h-sum/diff
        float h0s_d = w00d + w01d, h0d_d = w00d - w01d;   // (dw-diff)
        float h1s_s = w10s + w11s, h1d_s = w10s - w11s;
        float h1s_d = w10d + w11d, h1d_d = w10d - w11d;
        // T stage (dt): s = st*4 + sh*2 + sw
        res[0][lane] = (h0s_s + h1s_s) * SCALE;  // lll
        res[1][lane] = (h0s_d + h1s_d) * SCALE;  // llh
        res[2][lane] = (h0d_s + h1d_s) * SCALE;  // lhl
        res[3][lane] = (h0d_d + h1d_d) * SCALE;  // lhh
        res[4][lane] = (h0s_s - h1s_s) * SCALE;  // hll
        res[5][lane] = (h0s_d - h1s_d) * SCALE;  // hlh
        res[6][lane] = (h0d_s - h1d_s) * SCALE;  // hhl
        res[7][lane] = (h0d_d - h1d_d) * SCALE;  // hhh
    }

    // Output: channel = s*C + c ; write float2 (2 consecutive wp)
    int wp = w4 * 2;
    long outBase = (((long)b * (8 * C)) + c) * OUT_CH_STRIDE
                 + ((long)tp * Hp + hp) * Wp + wp;
    float2* __restrict__ o2 = (float2*)out;
    const long sStride2 = ((long)C * OUT_CH_STRIDE) / 2;  // float2 units per sub-band step
    long o = outBase / 2;
    #pragma unroll
    for (int s = 0; s < 8; s++) {
        o2[o + (long)s * sStride2] = make_float2(res[s][0], res[s][1]);
    }
}

extern "C" void kernel_launch(void* const* d_in, const int* in_sizes, int n_in,
                              void* d_out, int out_size) {
    const float* x = (const float*)d_in[0];
    float* out = (float*)d_out;
    (void)in_sizes; (void)n_in; (void)out_size;

    const int threads = 256;
    const long blocks = (TOTAL_THREADS + threads - 1) / threads;
    haar3d_kernel<<<(unsigned)blocks, threads>>>(x, out);
}

// round 2
// speedup vs baseline: 1.0102x; 1.0102x over previous
#include <cuda_runtime.h>
#include <cuda_bf16.h>

// Haar 3D wavelet transform, causal time pad (replicate first frame).
// x:  [B=2, C=3, T=33, H=512, W=512] fp32
// out:[B=2, 8*C=24, Tp=17, Hp=256, Wp=256] fp32, sub-band major (s*C + c)
//
// Each thread: 4 output wp positions (8 input floats along W),
// 8x LDG.128 front-batched, 8x STG.128 (one per sub-band).

#define SCALE 0.3536f

static constexpr int B  = 2;
static constexpr int C  = 3;
static constexpr int T  = 33;
static constexpr int H  = 512;
static constexpr int W  = 512;
static constexpr int Tp = 17;
static constexpr int Hp = 256;
static constexpr int Wp = 256;
static constexpr int WP4 = Wp / 4;   // 64: each thread covers 4 wp = 2 input float4s

static constexpr int TOTAL_THREADS = B * C * Tp * Hp * WP4;     // 1,671,168
static constexpr int OUT_CH_STRIDE = Tp * Hp * Wp;               // 1,114,112
static constexpr int IN_FRAME      = H * W;                      // 262,144
static constexpr int SSTRIDE4      = (C * OUT_CH_STRIDE) / 4;    // float4 step per sub-band

__global__ __launch_bounds__(256)
void haar3d_kernel(const float* __restrict__ x, float* __restrict__ out) {
    int idx = blockIdx.x * blockDim.x + threadIdx.x;
    if (idx >= TOTAL_THREADS) return;

    int w8 = idx & (WP4 - 1);          // [0,64): pair-of-float4 index along W
    int r  = idx >> 6;
    int hp = r & (Hp - 1); r >>= 8;
    int tp = r % Tp;
    int rc = r / Tp;
    int c  = rc % C;
    int b  = rc / C;

    int t1 = 2 * tp;                     // xp[2tp+1] -> x[2tp]
    int t0 = (t1 == 0) ? 0 : (t1 - 1);   // xp[2tp]   -> x[2tp-1] (clamped)
    int h0 = 2 * hp;

    const int inBase = (b * C + c) * T * IN_FRAME;
    const float4* __restrict__ x4 = (const float4*)x;
    int r00 = (inBase + t0 * IN_FRAME + (h0    ) * W) / 4 + w8 * 2;
    int r01 = (inBase + t0 * IN_FRAME + (h0 + 1) * W) / 4 + w8 * 2;
    int r10 = (inBase + t1 * IN_FRAME + (h0    ) * W) / 4 + w8 * 2;
    int r11 = (inBase + t1 * IN_FRAME + (h0 + 1) * W) / 4 + w8 * 2;

    // 8 front-batched streaming loads (MLP_p1 = 8)
    float4 a00 = __ldcs(&x4[r00]);
    float4 a01 = __ldcs(&x4[r01]);
    float4 a10 = __ldcs(&x4[r10]);
    float4 a11 = __ldcs(&x4[r11]);
    float4 b00 = __ldcs(&x4[r00 + 1]);
    float4 b01 = __ldcs(&x4[r01 + 1]);
    float4 b10 = __ldcs(&x4[r10 + 1]);
    float4 b11 = __ldcs(&x4[r11 + 1]);

    float res[8][4];   // [sub-band][output wp lane]

    #pragma unroll
    for (int j = 0; j < 2; j++) {       // which input float4 (2 output lanes each)
        float4 v00 = j ? b00 : a00;
        float4 v01 = j ? b01 : a01;
        float4 v10 = j ? b10 : a10;
        float4 v11 = j ? b11 : a11;
        #pragma unroll
        for (int lane = 0; lane < 2; lane++) {
            float p000, p001, p010, p011, p100, p101, p110, p111;
            if (lane == 0) {
                p000 = v00.x; p001 = v00.y;
                p010 = v01.x; p011 = v01.y;
                p100 = v10.x; p101 = v10.y;
                p110 = v11.x; p111 = v11.y;
            } else {
                p000 = v00.z; p001 = v00.w;
                p010 = v01.z; p011 = v01.w;
                p100 = v10.z; p101 = v10.w;
                p110 = v11.z; p111 = v11.w;
            }
            int ol = j * 2 + lane;
            // W stage
            float w00s = p000 + p001, w00d = p000 - p001;
            float w01s = p010 + p011, w01d = p010 - p011;
            float w10s = p100 + p101, w10d = p100 - p101;
            float w11s = p110 + p111, w11d = p110 - p111;
            // H stage
            float h0ss = w00s + w01s, h0ds = w00s - w01s;
            float h0sd = w00d + w01d, h0dd = w00d - w01d;
            float h1ss = w10s + w11s, h1ds = w10s - w11s;
            float h1sd = w10d + w11d, h1dd = w10d - w11d;
            // T stage: s = st*4 + sh*2 + sw
            res[0][ol] = (h0ss + h1ss) * SCALE;
            res[1][ol] = (h0sd + h1sd) * SCALE;
            res[2][ol] = (h0ds + h1ds) * SCALE;
            res[3][ol] = (h0dd + h1dd) * SCALE;
            res[4][ol] = (h0ss - h1ss) * SCALE;
            res[5][ol] = (h0sd - h1sd) * SCALE;
            res[6][ol] = (h0ds - h1ds) * SCALE;
            res[7][ol] = (h0dd - h1dd) * SCALE;
        }
    }

    // Output: channel = s*C + c ; one STG.128 per sub-band
    int wp = w8 * 4;
    int outBase4 = (((b * (8 * C)) + c) * OUT_CH_STRIDE
                   + (tp * Hp + hp) * Wp + wp) / 4;
    float4* __restrict__ o4 = (float4*)out;
    #pragma unroll
    for (int s = 0; s < 8; s++) {
        __stcs(&o4[outBase4 + s * SSTRIDE4],
               make_float4(res[s][0], res[s][1], res[s][2], res[s][3]));
    }
}

extern "C" void kernel_launch(void* const* d_in, const int* in_sizes, int n_in,
                              void* d_out, int out_size) {
    const float* x = (const float*)d_in[0];
    float* out = (float*)d_out;
    (void)in_sizes; (void)n_in; (void)out_size;

    const int threads = 256;
    const int blocks = (TOTAL_THREADS + threads - 1) / threads;
    haar3d_kernel<<<blocks, threads>>>(x, out);
}